// round 8
// baseline (speedup 1.0000x reference)
#include <cuda_runtime.h>
#include <cuda_bf16.h>
#include <cstddef>

#define N_NODES 100000
#define N_EDGES 1200000
#define HID 64
#define F_IN 16
#define G_GRAPHS 1024
#define CAP 96            // max in-degree capacity (Poisson(12): overflow ~1e-26)

// ---------------- scratch (device globals; no allocation) ----------------
__device__ float g_c1  [(size_t)N_NODES * F_IN];
__device__ float g_h1  [(size_t)N_NODES * HID];
__device__ float g_h2  [(size_t)N_NODES * HID];
__device__ int   g_deg [N_NODES];
__device__ int   g_bucket[(size_t)N_NODES * CAP];
__device__ float g_stats[3][2 * HID];
__device__ float g_pool[(size_t)G_GRAPHS * HID];
__device__ float g_cnt [G_GRAPHS];

// ---------------- tf32 helpers ----------------
__device__ __forceinline__ unsigned tf32_hi(float x) {
    unsigned r;
    asm("cvt.rna.tf32.f32 %0, %1;" : "=r"(r) : "f"(x));
    return r;
}

__device__ __forceinline__ void mma_tf32(float* c,
                                         unsigned a0, unsigned a1, unsigned a2, unsigned a3,
                                         unsigned b0, unsigned b1) {
    asm volatile(
        "mma.sync.aligned.m16n8k8.row.col.f32.tf32.tf32.f32 "
        "{%0,%1,%2,%3}, {%4,%5,%6,%7}, {%8,%9}, {%0,%1,%2,%3};"
        : "+f"(c[0]), "+f"(c[1]), "+f"(c[2]), "+f"(c[3])
        : "r"(a0), "r"(a1), "r"(a2), "r"(a3), "r"(b0), "r"(b1));
}

// BN scale/shift from accumulated sum/sumsq (training-mode batch stats)
__device__ __forceinline__ void bn_coeffs(const float* __restrict__ stats,
                                          const float* __restrict__ gamma,
                                          const float* __restrict__ beta,
                                          float* sc, float* sh) {
    int t = threadIdx.x;
    if (t < HID) {
        const float invN = 1.0f / (float)N_NODES;
        float mean = stats[t] * invN;
        float var  = stats[HID + t] * invN - mean * mean;
        float s    = gamma[t] * rsqrtf(var + 1e-5f);
        sc[t] = s;
        sh[t] = beta[t] - mean * s;
    }
}

// ---------------- zero pass ----------------
__global__ void zero_misc_kernel() {
    int i = blockIdx.x * blockDim.x + threadIdx.x;
    if (i < N_NODES)         g_deg[i] = 0;
    if (i < 3 * 2 * HID)     ((float*)g_stats)[i] = 0.0f;
    if (i < G_GRAPHS * HID)  g_pool[i] = 0.0f;
    if (i < G_GRAPHS)        g_cnt[i]  = 0.0f;
}

// ---------------- bucket build (once, reused by all 3 layers) ----------------
__global__ __launch_bounds__(256)
void bucket_kernel(const int* __restrict__ src, const int* __restrict__ dst) {
    int e = blockIdx.x * blockDim.x + threadIdx.x;
    if (e >= N_EDGES) return;
    int d = dst[e];
    int pos = atomicAdd(&g_deg[d], 1);
    if (pos < CAP) g_bucket[(size_t)d * CAP + pos] = src[e];
}

// ---------------- layer-1 gather-aggregate (16-wide, no BN) ----------------
__global__ __launch_bounds__(256)
void aggr16_kernel(const float* __restrict__ x,
                   const float* __restrict__ eps_p,
                   float* __restrict__ out) {
    int idx = blockIdx.x * blockDim.x + threadIdx.x;
    if (idx >= N_NODES * 4) return;
    int n = idx >> 2, q = idx & 3;
    int deg = min(g_deg[n], CAP);
    float epsv = 1.0f + *eps_p;
    float4 v = reinterpret_cast<const float4*>(x + (size_t)n * F_IN)[q];
    float4 a0 = make_float4(epsv * v.x, epsv * v.y, epsv * v.z, epsv * v.w);
    float4 a1 = make_float4(0, 0, 0, 0);
    const int* bk = g_bucket + (size_t)n * CAP;
    int i = 0;
    for (; i + 2 <= deg; i += 2) {
        int s0 = bk[i], s1 = bk[i + 1];
        float4 m0 = reinterpret_cast<const float4*>(x + (size_t)s0 * F_IN)[q];
        float4 m1 = reinterpret_cast<const float4*>(x + (size_t)s1 * F_IN)[q];
        a0.x += m0.x; a0.y += m0.y; a0.z += m0.z; a0.w += m0.w;
        a1.x += m1.x; a1.y += m1.y; a1.z += m1.z; a1.w += m1.w;
    }
    if (i < deg) {
        int s0 = bk[i];
        float4 m0 = reinterpret_cast<const float4*>(x + (size_t)s0 * F_IN)[q];
        a0.x += m0.x; a0.y += m0.y; a0.z += m0.z; a0.w += m0.w;
    }
    a0.x += a1.x; a0.y += a1.y; a0.z += a1.z; a0.w += a1.w;
    reinterpret_cast<float4*>(out + (size_t)n * F_IN)[q] = a0;
}

// ---------------- 64-wide gather-aggregate with BN fused ----------------
__global__ __launch_bounds__(256)
void aggr64_kernel(const float* __restrict__ h,
                   const float* __restrict__ stats,
                   const float* __restrict__ gamma,
                   const float* __restrict__ beta,
                   const float* __restrict__ eps_p,
                   float* __restrict__ out) {
    __shared__ float sc[HID], sh[HID];
    bn_coeffs(stats, gamma, beta, sc, sh);
    __syncthreads();

    int gw = (blockIdx.x * blockDim.x + threadIdx.x) >> 5;
    if (gw >= N_NODES) return;
    int lane = threadIdx.x & 31;
    float2 scl = *reinterpret_cast<const float2*>(&sc[2 * lane]);
    float2 shf = *reinterpret_cast<const float2*>(&sh[2 * lane]);

    int deg = min(g_deg[gw], CAP);
    float epsv = 1.0f + *eps_p;

    float2 v = reinterpret_cast<const float2*>(h + (size_t)gw * HID)[lane];
    float2 a0, a1 = {0, 0}, a2 = {0, 0}, a3 = {0, 0};
    a0.x = epsv * fmaf(v.x, scl.x, shf.x);
    a0.y = epsv * fmaf(v.y, scl.y, shf.y);

    const int* bk = g_bucket + (size_t)gw * CAP;
    for (int base = 0; base < deg; base += 32) {
        int cnt = min(32, deg - base);
        int s = 0;
        if (lane < cnt) s = bk[base + lane];
        int i = 0;
        for (; i + 4 <= cnt; i += 4) {
            int s0 = __shfl_sync(0xffffffffu, s, i);
            int s1 = __shfl_sync(0xffffffffu, s, i + 1);
            int s2 = __shfl_sync(0xffffffffu, s, i + 2);
            int s3 = __shfl_sync(0xffffffffu, s, i + 3);
            float2 m0 = reinterpret_cast<const float2*>(h + (size_t)s0 * HID)[lane];
            float2 m1 = reinterpret_cast<const float2*>(h + (size_t)s1 * HID)[lane];
            float2 m2 = reinterpret_cast<const float2*>(h + (size_t)s2 * HID)[lane];
            float2 m3 = reinterpret_cast<const float2*>(h + (size_t)s3 * HID)[lane];
            a0.x += fmaf(m0.x, scl.x, shf.x); a0.y += fmaf(m0.y, scl.y, shf.y);
            a1.x += fmaf(m1.x, scl.x, shf.x); a1.y += fmaf(m1.y, scl.y, shf.y);
            a2.x += fmaf(m2.x, scl.x, shf.x); a2.y += fmaf(m2.y, scl.y, shf.y);
            a3.x += fmaf(m3.x, scl.x, shf.x); a3.y += fmaf(m3.y, scl.y, shf.y);
        }
        for (; i < cnt; i++) {
            int s0 = __shfl_sync(0xffffffffu, s, i);
            float2 m0 = reinterpret_cast<const float2*>(h + (size_t)s0 * HID)[lane];
            a0.x += fmaf(m0.x, scl.x, shf.x); a0.y += fmaf(m0.y, scl.y, shf.y);
        }
    }
    a0.x += a1.x + a2.x + a3.x;
    a0.y += a1.y + a2.y + a3.y;
    reinterpret_cast<float2*>(out + (size_t)gw * HID)[lane] = a0;
}

// ---- GEMM [N,K]@[K,64] + bias + ReLU via tf32 MMA, hi/lo split (fp32 acc) ----
// 256 threads = 8 warps. Block tile 256 rows x 64 cols; warp tile 32 rows x 64
// (2 m16 tiles) so B fragments are reused across 2 m-tiles and hi/lo is derived
// in registers from a single fp32 W array (D = Ah*Bh + Al*Bh + Ah*Bl).
template <int K, bool STATS>
__global__ __launch_bounds__(256)
void gemm_mma_kernel(const float* __restrict__ X,
                     const float* __restrict__ W,
                     const float* __restrict__ bias,
                     float* __restrict__ out,
                     float* __restrict__ stats_out) {
    constexpr int SP  = K + 4;     // sIn stride: conflict-free A-frag loads
    constexpr int WSP = 72;        // sW stride: conflict-free B-frag loads
    extern __shared__ float smem[];
    float* sIn = smem;             // [256][SP]
    float* sW  = smem + 256 * SP;  // [K][WSP] (fp32; split in regs)
    __shared__ float sSum[HID], sSq[HID];

    const int tid  = threadIdx.x;
    const int w    = tid >> 5;
    const int lane = tid & 31;
    const int qid  = lane >> 2;    // 0..7
    const int tig  = lane & 3;     // 0..3
    const size_t row0 = (size_t)blockIdx.x * 256;

    if (STATS && tid < HID) { sSum[tid] = 0.0f; sSq[tid] = 0.0f; }

    for (int i = tid; i < K * 64; i += 256) {
        int k = i >> 6, n = i & 63;
        sW[k * WSP + n] = W[i];
    }
    for (int i = tid; i < 256 * K; i += 256) {
        int r = i / K, k = i - r * K;
        float v = 0.0f;
        if (row0 + r < N_NODES) v = X[row0 * K + i];
        sIn[r * SP + k] = v;
    }
    __syncthreads();

    float acc[2][8][4];
#pragma unroll
    for (int mt = 0; mt < 2; mt++)
#pragma unroll
        for (int nb = 0; nb < 8; nb++)
#pragma unroll
            for (int j = 0; j < 4; j++) acc[mt][nb][j] = 0.0f;

    const int rbase = w * 32;      // warp's first row in tile

#pragma unroll
    for (int kb = 0; kb < K / 8; kb++) {
        // ---- B fragments for all 8 n-blocks (hi/lo in regs) ----
        unsigned bh[8][2], bl[8][2];
#pragma unroll
        for (int nb = 0; nb < 8; nb++) {
            int off = (kb * 8 + tig) * WSP + nb * 8 + qid;
            float b0 = sW[off];
            float b1 = sW[off + 4 * WSP];
            bh[nb][0] = tf32_hi(b0);
            bh[nb][1] = tf32_hi(b1);
            bl[nb][0] = __float_as_uint(b0 - __uint_as_float(bh[nb][0]));
            bl[nb][1] = __float_as_uint(b1 - __uint_as_float(bh[nb][1]));
        }
        // ---- A fragments per m-tile, then 3-pass MMA ----
#pragma unroll
        for (int mt = 0; mt < 2; mt++) {
            const float* aB = &sIn[(rbase + mt * 16 + qid) * SP + kb * 8 + tig];
            float a0 = aB[0];
            float a1 = aB[8 * SP];
            float a2 = aB[4];
            float a3 = aB[8 * SP + 4];
            unsigned ah0 = tf32_hi(a0), ah1 = tf32_hi(a1);
            unsigned ah2 = tf32_hi(a2), ah3 = tf32_hi(a3);
            unsigned al0 = __float_as_uint(a0 - __uint_as_float(ah0));
            unsigned al1 = __float_as_uint(a1 - __uint_as_float(ah1));
            unsigned al2 = __float_as_uint(a2 - __uint_as_float(ah2));
            unsigned al3 = __float_as_uint(a3 - __uint_as_float(ah3));
#pragma unroll
            for (int nb = 0; nb < 8; nb++) {
                mma_tf32(acc[mt][nb], ah0, ah1, ah2, ah3, bh[nb][0], bh[nb][1]);
                mma_tf32(acc[mt][nb], al0, al1, al2, al3, bh[nb][0], bh[nb][1]);
                mma_tf32(acc[mt][nb], ah0, ah1, ah2, ah3, bl[nb][0], bl[nb][1]);
            }
        }
    }

    // ---- epilogue: bias + relu + store + stats ----
#pragma unroll
    for (int mt = 0; mt < 2; mt++) {
        const size_t r1 = row0 + rbase + mt * 16 + qid;
        const size_t r2 = r1 + 8;
#pragma unroll
        for (int nb = 0; nb < 8; nb++) {
            int col = nb * 8 + 2 * tig;
            float2 b = *reinterpret_cast<const float2*>(bias + col);
            float s0 = 0.0f, s1 = 0.0f, q0 = 0.0f, q1 = 0.0f;
            if (r1 < N_NODES) {
                float o0 = fmaxf(acc[mt][nb][0] + b.x, 0.0f);
                float o1 = fmaxf(acc[mt][nb][1] + b.y, 0.0f);
                *reinterpret_cast<float2*>(out + r1 * 64 + col) = make_float2(o0, o1);
                s0 += o0; s1 += o1; q0 += o0 * o0; q1 += o1 * o1;
            }
            if (r2 < N_NODES) {
                float o0 = fmaxf(acc[mt][nb][2] + b.x, 0.0f);
                float o1 = fmaxf(acc[mt][nb][3] + b.y, 0.0f);
                *reinterpret_cast<float2*>(out + r2 * 64 + col) = make_float2(o0, o1);
                s0 += o0; s1 += o1; q0 += o0 * o0; q1 += o1 * o1;
            }
            if (STATS) {
                atomicAdd(&sSum[col],     s0);
                atomicAdd(&sSum[col + 1], s1);
                atomicAdd(&sSq[col],      q0);
                atomicAdd(&sSq[col + 1],  q1);
            }
        }
    }

    if (STATS) {
        __syncthreads();
        if (tid < HID) {
            atomicAdd(&stats_out[tid],       sSum[tid]);
            atomicAdd(&stats_out[HID + tid], sSq[tid]);
        }
    }
}

// ---------------- pool with final BN fused ----------------
__global__ __launch_bounds__(256)
void pool_bn_kernel(const float* __restrict__ h,
                    const int* __restrict__ batch,
                    const float* __restrict__ stats,
                    const float* __restrict__ gamma,
                    const float* __restrict__ beta) {
    __shared__ float sc[HID], sh[HID];
    bn_coeffs(stats, gamma, beta, sc, sh);
    __syncthreads();
    int idx = blockIdx.x * blockDim.x + threadIdx.x;
    if (idx >= N_NODES * 16) return;
    int n = idx >> 4, q = idx & 15;
    int g = batch[n];
    float4 v = reinterpret_cast<const float4*>(h)[idx];
    int f = q * 4;
    v.x = v.x * sc[f    ] + sh[f    ];
    v.y = v.y * sc[f + 1] + sh[f + 1];
    v.z = v.z * sc[f + 2] + sh[f + 2];
    v.w = v.w * sc[f + 3] + sh[f + 3];
    atomicAdd(reinterpret_cast<float4*>(g_pool) + (size_t)g * 16 + q, v);
    if (q == 0) atomicAdd(&g_cnt[g], 1.0f);
}

// ---------------- readout MLP ----------------
__global__ void readout_kernel(const float* __restrict__ Wf1,
                               const float* __restrict__ bf1,
                               const float* __restrict__ Wf2,
                               const float* __restrict__ bf2,
                               float* __restrict__ out) {
    int g = blockIdx.x * blockDim.x + threadIdx.x;
    if (g >= G_GRAPHS) return;
    float inv = 1.0f / fmaxf(g_cnt[g], 1.0f);
    float hid[10];
#pragma unroll
    for (int j = 0; j < 10; j++) hid[j] = bf1[j];
    for (int k = 0; k < 64; k++) {
        float p = g_pool[(size_t)g * 64 + k] * inv;
#pragma unroll
        for (int j = 0; j < 10; j++) hid[j] += p * Wf1[k * 10 + j];
    }
    float o = bf2[0];
#pragma unroll
    for (int j = 0; j < 10; j++) o += fmaxf(hid[j], 0.0f) * Wf2[j];
    out[g] = o;
}

// ---------------- host launcher ----------------
static inline int cdiv(long long a, int b) { return (int)((a + b - 1) / b); }

extern "C" void kernel_launch(void* const* d_in, const int* in_sizes, int n_in,
                              void* d_out, int out_size) {
    (void)in_sizes; (void)n_in; (void)out_size;
    const float* x     = (const float*)d_in[0];
    const int*   ei    = (const int*)  d_in[1];
    const int*   batch = (const int*)  d_in[2];
    const float* W1a = (const float*)d_in[3];  const float* b1a = (const float*)d_in[4];
    const float* W1b = (const float*)d_in[5];  const float* b1b = (const float*)d_in[6];
    const float* e1  = (const float*)d_in[7];
    const float* g1  = (const float*)d_in[8];  const float* be1 = (const float*)d_in[9];
    const float* W2a = (const float*)d_in[10]; const float* b2a = (const float*)d_in[11];
    const float* W2b = (const float*)d_in[12]; const float* b2b = (const float*)d_in[13];
    const float* e2  = (const float*)d_in[14];
    const float* g2  = (const float*)d_in[15]; const float* be2 = (const float*)d_in[16];
    const float* W3a = (const float*)d_in[17]; const float* b3a = (const float*)d_in[18];
    const float* W3b = (const float*)d_in[19]; const float* b3b = (const float*)d_in[20];
    const float* e3  = (const float*)d_in[21];
    const float* g3  = (const float*)d_in[22]; const float* be3 = (const float*)d_in[23];
    const float* Wf1 = (const float*)d_in[24]; const float* bf1 = (const float*)d_in[25];
    const float* Wf2 = (const float*)d_in[26]; const float* bf2 = (const float*)d_in[27];
    float* out = (float*)d_out;

    const int* src = ei;
    const int* dst = ei + N_EDGES;

    void *p_c1, *p_h1, *p_h2, *p_stats;
    cudaGetSymbolAddress(&p_c1, g_c1);
    cudaGetSymbolAddress(&p_h1, g_h1);
    cudaGetSymbolAddress(&p_h2, g_h2);
    cudaGetSymbolAddress(&p_stats, g_stats);
    float* c1 = (float*)p_c1;
    float* h1 = (float*)p_h1;
    float* h2 = (float*)p_h2;
    float* st0 = (float*)p_stats;
    float* st1 = st0 + 2 * HID;
    float* st2 = st0 + 4 * HID;

    const int TB = 256;
    const int GB = cdiv(N_NODES, 256);   // 391

    const int smem16 = (256 * (F_IN + 4) + F_IN * 72) * 4;   // ~25KB
    const int smem64 = (256 * (HID + 4) + HID * 72) * 4;     // ~88KB
    cudaFuncSetAttribute((const void*)gemm_mma_kernel<F_IN, false>,
                         cudaFuncAttributeMaxDynamicSharedMemorySize, smem16);
    cudaFuncSetAttribute((const void*)gemm_mma_kernel<HID, false>,
                         cudaFuncAttributeMaxDynamicSharedMemorySize, smem64);
    cudaFuncSetAttribute((const void*)gemm_mma_kernel<HID, true>,
                         cudaFuncAttributeMaxDynamicSharedMemorySize, smem64);

    zero_misc_kernel<<<cdiv(N_NODES, TB), TB>>>();
    bucket_kernel<<<cdiv(N_EDGES, TB), TB>>>(src, dst);

    // ===== layer 1 =====
    aggr16_kernel<<<cdiv(N_NODES * 4, TB), TB>>>(x, e1, c1);
    gemm_mma_kernel<F_IN, false><<<GB, TB, smem16>>>(c1, W1a, b1a, h1, nullptr);
    gemm_mma_kernel<HID,  true ><<<GB, TB, smem64>>>(h1, W1b, b1b, h2, st0);

    // ===== layer 2 =====
    aggr64_kernel<<<cdiv(N_NODES * 32, TB), TB>>>(h2, st0, g1, be1, e2, h1);
    gemm_mma_kernel<HID, false><<<GB, TB, smem64>>>(h1, W2a, b2a, h2, nullptr);
    gemm_mma_kernel<HID, true ><<<GB, TB, smem64>>>(h2, W2b, b2b, h1, st1);

    // ===== layer 3 =====
    aggr64_kernel<<<cdiv(N_NODES * 32, TB), TB>>>(h1, st1, g2, be2, e3, h2);
    gemm_mma_kernel<HID, false><<<GB, TB, smem64>>>(h2, W3a, b3a, h1, nullptr);
    gemm_mma_kernel<HID, true ><<<GB, TB, smem64>>>(h1, W3b, b3b, h2, st2);

    // ===== pool + readout (BN3 fused into pool) =====
    pool_bn_kernel<<<cdiv(N_NODES * 16, TB), TB>>>(h2, batch, st2, g3, be3);
    readout_kernel<<<cdiv(G_GRAPHS, TB), TB>>>(Wf1, bf1, Wf2, bf2, out);
}

// round 9
// speedup vs baseline: 1.6488x; 1.6488x over previous
#include <cuda_runtime.h>
#include <cuda_bf16.h>
#include <cstddef>

#define N_NODES 100000
#define N_EDGES 1200000
#define HID 64
#define F_IN 16
#define G_GRAPHS 1024
#define CAP 96            // max in-degree capacity (Poisson(12): overflow ~1e-26)

// ---------------- scratch (device globals; no allocation) ----------------
__device__ float g_c1  [(size_t)N_NODES * F_IN];
__device__ float g_h1  [(size_t)N_NODES * HID];
__device__ float g_h2  [(size_t)N_NODES * HID];
__device__ int   g_deg [N_NODES];
__device__ int   g_bucket[(size_t)N_NODES * CAP];
__device__ float g_stats[3][2 * HID];

// BN scale/shift from accumulated sum/sumsq (training-mode batch stats)
__device__ __forceinline__ void bn_coeffs(const float* __restrict__ stats,
                                          const float* __restrict__ gamma,
                                          const float* __restrict__ beta,
                                          float* sc, float* sh) {
    int t = threadIdx.x;
    if (t < HID) {
        const float invN = 1.0f / (float)N_NODES;
        float mean = stats[t] * invN;
        float var  = stats[HID + t] * invN - mean * mean;
        float s    = gamma[t] * rsqrtf(var + 1e-5f);
        sc[t] = s;
        sh[t] = beta[t] - mean * s;
    }
}

// ---------------- zero pass ----------------
__global__ void zero_misc_kernel() {
    int i = blockIdx.x * blockDim.x + threadIdx.x;
    if (i < N_NODES)     g_deg[i] = 0;
    if (i < 3 * 2 * HID) ((float*)g_stats)[i] = 0.0f;
}

// ---------------- bucket build (once, reused by all 3 layers) ----------------
__global__ __launch_bounds__(256)
void bucket_kernel(const int* __restrict__ src, const int* __restrict__ dst) {
    int e = blockIdx.x * blockDim.x + threadIdx.x;
    if (e >= N_EDGES) return;
    int d = dst[e];
    int pos = atomicAdd(&g_deg[d], 1);
    if (pos < CAP) g_bucket[(size_t)d * CAP + pos] = src[e];
}

// ---------------- layer-1 gather-aggregate (16-wide, no BN) ----------------
__global__ __launch_bounds__(256)
void aggr16_kernel(const float* __restrict__ x,
                   const float* __restrict__ eps_p,
                   float* __restrict__ out) {
    int idx = blockIdx.x * blockDim.x + threadIdx.x;
    if (idx >= N_NODES * 4) return;
    int n = idx >> 2, q = idx & 3;
    int deg = min(g_deg[n], CAP);
    float epsv = 1.0f + *eps_p;
    float4 v = reinterpret_cast<const float4*>(x + (size_t)n * F_IN)[q];
    float4 a0 = make_float4(epsv * v.x, epsv * v.y, epsv * v.z, epsv * v.w);
    float4 a1 = make_float4(0, 0, 0, 0);
    const int* bk = g_bucket + (size_t)n * CAP;
    int i = 0;
    for (; i + 2 <= deg; i += 2) {
        int s0 = bk[i], s1 = bk[i + 1];
        float4 m0 = reinterpret_cast<const float4*>(x + (size_t)s0 * F_IN)[q];
        float4 m1 = reinterpret_cast<const float4*>(x + (size_t)s1 * F_IN)[q];
        a0.x += m0.x; a0.y += m0.y; a0.z += m0.z; a0.w += m0.w;
        a1.x += m1.x; a1.y += m1.y; a1.z += m1.z; a1.w += m1.w;
    }
    if (i < deg) {
        int s0 = bk[i];
        float4 m0 = reinterpret_cast<const float4*>(x + (size_t)s0 * F_IN)[q];
        a0.x += m0.x; a0.y += m0.y; a0.z += m0.z; a0.w += m0.w;
    }
    a0.x += a1.x; a0.y += a1.y; a0.z += a1.z; a0.w += a1.w;
    reinterpret_cast<float4*>(out + (size_t)n * F_IN)[q] = a0;
}

// ---------------- 64-wide gather-aggregate with BN fused ----------------
__global__ __launch_bounds__(256)
void aggr64_kernel(const float* __restrict__ h,
                   const float* __restrict__ stats,
                   const float* __restrict__ gamma,
                   const float* __restrict__ beta,
                   const float* __restrict__ eps_p,
                   float* __restrict__ out) {
    __shared__ float sc[HID], sh[HID];
    bn_coeffs(stats, gamma, beta, sc, sh);
    __syncthreads();

    int gw = (blockIdx.x * blockDim.x + threadIdx.x) >> 5;
    if (gw >= N_NODES) return;
    int lane = threadIdx.x & 31;
    float2 scl = *reinterpret_cast<const float2*>(&sc[2 * lane]);
    float2 shf = *reinterpret_cast<const float2*>(&sh[2 * lane]);

    int deg = min(g_deg[gw], CAP);
    float epsv = 1.0f + *eps_p;

    float2 v = reinterpret_cast<const float2*>(h + (size_t)gw * HID)[lane];
    float2 a0, a1 = {0, 0}, a2 = {0, 0}, a3 = {0, 0};
    a0.x = epsv * fmaf(v.x, scl.x, shf.x);
    a0.y = epsv * fmaf(v.y, scl.y, shf.y);

    const int* bk = g_bucket + (size_t)gw * CAP;
    for (int base = 0; base < deg; base += 32) {
        int cnt = min(32, deg - base);
        int s = 0;
        if (lane < cnt) s = bk[base + lane];
        int i = 0;
        for (; i + 4 <= cnt; i += 4) {
            int s0 = __shfl_sync(0xffffffffu, s, i);
            int s1 = __shfl_sync(0xffffffffu, s, i + 1);
            int s2 = __shfl_sync(0xffffffffu, s, i + 2);
            int s3 = __shfl_sync(0xffffffffu, s, i + 3);
            float2 m0 = reinterpret_cast<const float2*>(h + (size_t)s0 * HID)[lane];
            float2 m1 = reinterpret_cast<const float2*>(h + (size_t)s1 * HID)[lane];
            float2 m2 = reinterpret_cast<const float2*>(h + (size_t)s2 * HID)[lane];
            float2 m3 = reinterpret_cast<const float2*>(h + (size_t)s3 * HID)[lane];
            a0.x += fmaf(m0.x, scl.x, shf.x); a0.y += fmaf(m0.y, scl.y, shf.y);
            a1.x += fmaf(m1.x, scl.x, shf.x); a1.y += fmaf(m1.y, scl.y, shf.y);
            a2.x += fmaf(m2.x, scl.x, shf.x); a2.y += fmaf(m2.y, scl.y, shf.y);
            a3.x += fmaf(m3.x, scl.x, shf.x); a3.y += fmaf(m3.y, scl.y, shf.y);
        }
        for (; i < cnt; i++) {
            int s0 = __shfl_sync(0xffffffffu, s, i);
            float2 m0 = reinterpret_cast<const float2*>(h + (size_t)s0 * HID)[lane];
            a0.x += fmaf(m0.x, scl.x, shf.x); a0.y += fmaf(m0.y, scl.y, shf.y);
        }
    }
    a0.x += a1.x + a2.x + a3.x;
    a0.y += a1.y + a2.y + a3.y;
    reinterpret_cast<float2*>(out + (size_t)gw * HID)[lane] = a0;
}

// ---------------- GEMM [N,K]@[K,64] + bias + ReLU (R4 scalar tile) ----------
// 256 threads; tile ROWS x 64; thread: (ROWS/16) rows x 4 cols; k-vec by 4.
template <int K, int ROWS, int MINB, bool STATS>
__global__ __launch_bounds__(256, MINB)
void gemm_kernel(const float* __restrict__ X,
                 const float* __restrict__ W,
                 const float* __restrict__ bias,
                 float* __restrict__ out,
                 float* __restrict__ stats_out) {
    constexpr int RJ = ROWS / 16;
    __shared__ float sW[K * 64];
    __shared__ float sIn[ROWS * K];
    __shared__ float sSum[HID], sSq[HID];

    const int tid = threadIdx.x;
    const int tx  = tid & 15;
    const int ty  = tid >> 4;
    const size_t row0 = (size_t)blockIdx.x * ROWS;

    if (STATS && tid < HID) { sSum[tid] = 0.0f; sSq[tid] = 0.0f; }

    for (int i = tid; i < K * 64; i += 256) sW[i] = W[i];

    for (int i = tid; i < ROWS * K; i += 256) {
        size_t r = row0 + (size_t)(i / K);
        sIn[i] = (r < N_NODES) ? X[row0 * K + i] : 0.0f;
    }
    __syncthreads();

    float4 acc[RJ];
#pragma unroll
    for (int j = 0; j < RJ; j++) acc[j] = make_float4(0, 0, 0, 0);

#pragma unroll
    for (int k = 0; k < K; k += 4) {
        float4 w0 = *reinterpret_cast<const float4*>(&sW[(k + 0) * 64 + tx * 4]);
        float4 w1 = *reinterpret_cast<const float4*>(&sW[(k + 1) * 64 + tx * 4]);
        float4 w2 = *reinterpret_cast<const float4*>(&sW[(k + 2) * 64 + tx * 4]);
        float4 w3 = *reinterpret_cast<const float4*>(&sW[(k + 3) * 64 + tx * 4]);
#pragma unroll
        for (int j = 0; j < RJ; j++) {
            float4 a = *reinterpret_cast<const float4*>(&sIn[(ty * RJ + j) * K + k]);
            acc[j].x = fmaf(a.x, w0.x, acc[j].x);
            acc[j].y = fmaf(a.x, w0.y, acc[j].y);
            acc[j].z = fmaf(a.x, w0.z, acc[j].z);
            acc[j].w = fmaf(a.x, w0.w, acc[j].w);
            acc[j].x = fmaf(a.y, w1.x, acc[j].x);
            acc[j].y = fmaf(a.y, w1.y, acc[j].y);
            acc[j].z = fmaf(a.y, w1.z, acc[j].z);
            acc[j].w = fmaf(a.y, w1.w, acc[j].w);
            acc[j].x = fmaf(a.z, w2.x, acc[j].x);
            acc[j].y = fmaf(a.z, w2.y, acc[j].y);
            acc[j].z = fmaf(a.z, w2.z, acc[j].z);
            acc[j].w = fmaf(a.z, w2.w, acc[j].w);
            acc[j].x = fmaf(a.w, w3.x, acc[j].x);
            acc[j].y = fmaf(a.w, w3.y, acc[j].y);
            acc[j].z = fmaf(a.w, w3.z, acc[j].z);
            acc[j].w = fmaf(a.w, w3.w, acc[j].w);
        }
    }

    const float4 bv = reinterpret_cast<const float4*>(bias)[tx];
    float4 ls = make_float4(0, 0, 0, 0), lss = make_float4(0, 0, 0, 0);
#pragma unroll
    for (int j = 0; j < RJ; j++) {
        size_t row = row0 + ty * RJ + j;
        if (row >= N_NODES) break;
        float4 o;
        o.x = fmaxf(acc[j].x + bv.x, 0.0f);
        o.y = fmaxf(acc[j].y + bv.y, 0.0f);
        o.z = fmaxf(acc[j].z + bv.z, 0.0f);
        o.w = fmaxf(acc[j].w + bv.w, 0.0f);
        reinterpret_cast<float4*>(out + row * 64)[tx] = o;
        if (STATS) {
            ls.x += o.x; ls.y += o.y; ls.z += o.z; ls.w += o.w;
            lss.x += o.x * o.x; lss.y += o.y * o.y;
            lss.z += o.z * o.z; lss.w += o.w * o.w;
        }
    }

    if (STATS) {
        atomicAdd(&sSum[tx * 4 + 0], ls.x);
        atomicAdd(&sSum[tx * 4 + 1], ls.y);
        atomicAdd(&sSum[tx * 4 + 2], ls.z);
        atomicAdd(&sSum[tx * 4 + 3], ls.w);
        atomicAdd(&sSq[tx * 4 + 0], lss.x);
        atomicAdd(&sSq[tx * 4 + 1], lss.y);
        atomicAdd(&sSq[tx * 4 + 2], lss.z);
        atomicAdd(&sSq[tx * 4 + 3], lss.w);
        __syncthreads();
        if (tid < HID) {
            atomicAdd(&stats_out[tid],       sSum[tid]);
            atomicAdd(&stats_out[HID + tid], sSq[tid]);
        }
    }
}

// ---------------- fused BN3 + mean-pool + readout (batch is sorted) ---------
// One block per graph: binary-search the node segment, segment-sum, apply the
// BN affine to the mean (affine commutes with mean), then 64->10->1 MLP.
__global__ __launch_bounds__(128)
void pool_readout_kernel(const float* __restrict__ h,
                         const int* __restrict__ batch,
                         const float* __restrict__ stats,
                         const float* __restrict__ gamma,
                         const float* __restrict__ beta,
                         const float* __restrict__ Wf1,
                         const float* __restrict__ bf1,
                         const float* __restrict__ Wf2,
                         const float* __restrict__ bf2,
                         float* __restrict__ out) {
    __shared__ float sc[HID], sh[HID];
    __shared__ float part[4][HID];
    __shared__ float pooled[HID];
    __shared__ float hid[10];

    const int g   = blockIdx.x;
    const int tid = threadIdx.x;

    if (tid < HID) {
        const float invN = 1.0f / (float)N_NODES;
        float mean = stats[tid] * invN;
        float var  = stats[HID + tid] * invN - mean * mean;
        float s    = gamma[tid] * rsqrtf(var + 1e-5f);
        sc[tid] = s;
        sh[tid] = beta[tid] - mean * s;
    }

    // segment bounds via binary search (batch sorted ascending)
    int lo = 0, hi = N_NODES;
    while (lo < hi) { int m = (lo + hi) >> 1; if (batch[m] < g)     lo = m + 1; else hi = m; }
    const int start = lo;
    lo = start; hi = N_NODES;
    while (lo < hi) { int m = (lo + hi) >> 1; if (batch[m] < g + 1) lo = m + 1; else hi = m; }
    const int end = lo;

    const int cp = tid & 31;     // column pair
    const int rg = tid >> 5;     // row group 0..3
    float2 a = make_float2(0, 0);
    for (int r = start + rg; r < end; r += 4) {
        float2 v = reinterpret_cast<const float2*>(h + (size_t)r * HID)[cp];
        a.x += v.x; a.y += v.y;
    }
    part[rg][cp * 2]     = a.x;
    part[rg][cp * 2 + 1] = a.y;
    __syncthreads();

    if (tid < 32) {
        float inv = 1.0f / fmaxf((float)(end - start), 1.0f);
        int c = tid * 2;
        float sx = part[0][c] + part[1][c] + part[2][c] + part[3][c];
        float sy = part[0][c + 1] + part[1][c + 1] + part[2][c + 1] + part[3][c + 1];
        pooled[c]     = (sx * inv) * sc[c]     + sh[c];
        pooled[c + 1] = (sy * inv) * sc[c + 1] + sh[c + 1];
    }
    __syncthreads();

    if (tid < 10) {
        float acc = bf1[tid];
        for (int k = 0; k < 64; k++) acc += pooled[k] * Wf1[k * 10 + tid];
        hid[tid] = fmaxf(acc, 0.0f);
    }
    __syncthreads();

    if (tid == 0) {
        float o = bf2[0];
#pragma unroll
        for (int j = 0; j < 10; j++) o += hid[j] * Wf2[j];
        out[g] = o;
    }
}

// ---------------- host launcher ----------------
static inline int cdiv(long long a, int b) { return (int)((a + b - 1) / b); }

extern "C" void kernel_launch(void* const* d_in, const int* in_sizes, int n_in,
                              void* d_out, int out_size) {
    (void)in_sizes; (void)n_in; (void)out_size;
    const float* x     = (const float*)d_in[0];
    const int*   ei    = (const int*)  d_in[1];
    const int*   batch = (const int*)  d_in[2];
    const float* W1a = (const float*)d_in[3];  const float* b1a = (const float*)d_in[4];
    const float* W1b = (const float*)d_in[5];  const float* b1b = (const float*)d_in[6];
    const float* e1  = (const float*)d_in[7];
    const float* g1  = (const float*)d_in[8];  const float* be1 = (const float*)d_in[9];
    const float* W2a = (const float*)d_in[10]; const float* b2a = (const float*)d_in[11];
    const float* W2b = (const float*)d_in[12]; const float* b2b = (const float*)d_in[13];
    const float* e2  = (const float*)d_in[14];
    const float* g2  = (const float*)d_in[15]; const float* be2 = (const float*)d_in[16];
    const float* W3a = (const float*)d_in[17]; const float* b3a = (const float*)d_in[18];
    const float* W3b = (const float*)d_in[19]; const float* b3b = (const float*)d_in[20];
    const float* e3  = (const float*)d_in[21];
    const float* g3  = (const float*)d_in[22]; const float* be3 = (const float*)d_in[23];
    const float* Wf1 = (const float*)d_in[24]; const float* bf1 = (const float*)d_in[25];
    const float* Wf2 = (const float*)d_in[26]; const float* bf2 = (const float*)d_in[27];
    float* out = (float*)d_out;

    const int* src = ei;
    const int* dst = ei + N_EDGES;

    void *p_c1, *p_h1, *p_h2, *p_stats;
    cudaGetSymbolAddress(&p_c1, g_c1);
    cudaGetSymbolAddress(&p_h1, g_h1);
    cudaGetSymbolAddress(&p_h2, g_h2);
    cudaGetSymbolAddress(&p_stats, g_stats);
    float* c1 = (float*)p_c1;
    float* h1 = (float*)p_h1;
    float* h2 = (float*)p_h2;
    float* st0 = (float*)p_stats;
    float* st1 = st0 + 2 * HID;
    float* st2 = st0 + 4 * HID;

    const int TB = 256;
    const int GB16 = cdiv(N_NODES, 64);    // 1563 (gemm16: more blocks, latency hiding)
    const int GB64 = cdiv(N_NODES, 128);   // 782  (gemm64: proven at FFMA floor)

    zero_misc_kernel<<<cdiv(N_NODES, TB), TB>>>();
    bucket_kernel<<<cdiv(N_EDGES, TB), TB>>>(src, dst);

    // ===== layer 1 =====
    aggr16_kernel<<<cdiv(N_NODES * 4, TB), TB>>>(x, e1, c1);
    gemm_kernel<F_IN, 64, 4, false><<<GB16, TB>>>(c1, W1a, b1a, h1, nullptr);
    gemm_kernel<HID, 128, 3, true ><<<GB64, TB>>>(h1, W1b, b1b, h2, st0);

    // ===== layer 2 =====
    aggr64_kernel<<<cdiv(N_NODES * 32, TB), TB>>>(h2, st0, g1, be1, e2, h1);
    gemm_kernel<HID, 128, 3, false><<<GB64, TB>>>(h1, W2a, b2a, h2, nullptr);
    gemm_kernel<HID, 128, 3, true ><<<GB64, TB>>>(h2, W2b, b2b, h1, st1);

    // ===== layer 3 =====
    aggr64_kernel<<<cdiv(N_NODES * 32, TB), TB>>>(h1, st1, g2, be2, e3, h2);
    gemm_kernel<HID, 128, 3, false><<<GB64, TB>>>(h2, W3a, b3a, h1, nullptr);
    gemm_kernel<HID, 128, 3, true ><<<GB64, TB>>>(h1, W3b, b3b, h2, st2);

    // ===== fused BN3 + mean-pool + readout =====
    pool_readout_kernel<<<G_GRAPHS, 128>>>(h2, batch, st2, g3, be3,
                                           Wf1, bf1, Wf2, bf2, out);
}